// round 1
// baseline (speedup 1.0000x reference)
#include <cuda_runtime.h>
#include <cuda_bf16.h>
#include <math.h>

// Problem constants (fixed by the dataset)
#define NN 100000
#define EE 1600000
#define MAXD 112

// ---------------- device scratch (no allocation allowed) ----------------
__device__ int   g_cnt[NN];
__device__ int   g_cursor[NN];
__device__ int   g_rowptr[NN + 1];
__device__ int   g_col[EE];
__device__ float g_dinv[NN];
__device__ float g_hs[(size_t)NN * MAXD];   // GEMM output, pre-scaled by dinv[row]
__device__ float g_ag[(size_t)NN * 64];     // aggregation output (hidden layers)

// ---------------- graph preprocessing ----------------
__global__ void zero_kernel(int n) {
    int i = blockIdx.x * blockDim.x + threadIdx.x;
    if (i < n) { g_cnt[i] = 0; g_cursor[i] = 0; }
}

__global__ void hist_kernel(const int* __restrict__ dst, int e) {
    int i = blockIdx.x * blockDim.x + threadIdx.x;
    if (i < e) atomicAdd(&g_cnt[dst[i]], 1);
}

// single-block exclusive scan of g_cnt -> g_rowptr (n up to 100000)
__global__ void scan_kernel(int n) {
    __shared__ int sh[1024];
    __shared__ int carry;
    int tid = threadIdx.x;
    if (tid == 0) carry = 0;
    __syncthreads();
    for (int base = 0; base < n; base += 1024) {
        int v = (base + tid < n) ? g_cnt[base + tid] : 0;
        sh[tid] = v;
        __syncthreads();
        #pragma unroll
        for (int off = 1; off < 1024; off <<= 1) {
            int t = (tid >= off) ? sh[tid - off] : 0;
            __syncthreads();
            sh[tid] += t;
            __syncthreads();
        }
        int incl = sh[tid];
        if (base + tid < n) g_rowptr[base + tid] = carry + incl - v;
        __syncthreads();
        if (tid == 1023) carry += sh[1023];
        __syncthreads();
    }
    if (tid == 0) g_rowptr[n] = carry;
}

__global__ void dinv_kernel(int n) {
    int i = blockIdx.x * blockDim.x + threadIdx.x;
    if (i < n) g_dinv[i] = rsqrtf((float)(g_cnt[i] + 1));  // +1 self loop
}

__global__ void scatter_kernel(const int* __restrict__ src,
                               const int* __restrict__ dst, int e) {
    int i = blockIdx.x * blockDim.x + threadIdx.x;
    if (i < e) {
        int d = dst[i];
        int pos = g_rowptr[d] + atomicAdd(&g_cursor[d], 1);
        g_col[pos] = src[i];
    }
}

// ---------------- GEMM: out[r, c] = dinv[r] * sum_k X[r,k] W[k,c] ----------------
#define BM 64
#define BN 64
#define BK 16
__global__ void gemm_scale_kernel(const float* __restrict__ X,
                                  const float* __restrict__ W,
                                  float* __restrict__ out,
                                  int M, int K, int Nn) {
    __shared__ float Xs[BM][BK + 1];
    __shared__ float Ws[BK][BN];
    int tid = threadIdx.x;
    int rowbase = blockIdx.y * BM;
    int colbase = blockIdx.x * BN;
    int tcol = tid & 15;        // 0..15
    int trow = tid >> 4;        // 0..15
    float acc[4][4] = {};
    for (int kb = 0; kb < K; kb += BK) {
        #pragma unroll
        for (int l = 0; l < 4; l++) {
            int idx = tid + l * 256;
            int r = idx >> 4, c = idx & 15;
            int gr = rowbase + r;
            Xs[r][c] = (gr < M) ? X[(size_t)gr * K + kb + c] : 0.f;
        }
        #pragma unroll
        for (int l = 0; l < 4; l++) {
            int idx = tid + l * 256;
            int r = idx >> 6, c = idx & 63;
            int gc = colbase + c;
            Ws[r][c] = (gc < Nn) ? W[(size_t)(kb + r) * Nn + gc] : 0.f;
        }
        __syncthreads();
        #pragma unroll
        for (int k = 0; k < BK; k++) {
            float a[4], b[4];
            #pragma unroll
            for (int i = 0; i < 4; i++) a[i] = Xs[trow * 4 + i][k];
            float4 bv = *reinterpret_cast<const float4*>(&Ws[k][tcol * 4]);
            b[0] = bv.x; b[1] = bv.y; b[2] = bv.z; b[3] = bv.w;
            #pragma unroll
            for (int i = 0; i < 4; i++)
                #pragma unroll
                for (int j = 0; j < 4; j++)
                    acc[i][j] = fmaf(a[i], b[j], acc[i][j]);
        }
        __syncthreads();
    }
    #pragma unroll
    for (int i = 0; i < 4; i++) {
        int gr = rowbase + trow * 4 + i;
        if (gr >= M) continue;
        float dv = g_dinv[gr];
        #pragma unroll
        for (int j = 0; j < 4; j++) {
            int gc = colbase + tcol * 4 + j;
            if (gc < Nn) out[(size_t)gr * Nn + gc] = acc[i][j] * dv;
        }
    }
}

// ---------------- aggregation: one warp per node, gather-only ----------------
// out[v,f] = dinv[v] * ( sum_{u in N(v)} hs[u,f] + hs[v,f] ) + bias[f]   (opt relu)
__global__ void agg_kernel(const float* __restrict__ hs,
                           const float* __restrict__ bias,
                           float* __restrict__ out,
                           int n, int D, int relu) {
    int w = (blockIdx.x * blockDim.x + threadIdx.x) >> 5;
    int lane = threadIdx.x & 31;
    if (w >= n) return;
    float acc[4] = {0.f, 0.f, 0.f, 0.f};
    const float* hv = hs + (size_t)w * D;
    #pragma unroll
    for (int j = 0; j < 4; j++) {
        int f = j * 32 + lane;
        if (f < D) acc[j] = __ldg(&hv[f]);   // self-loop term (already dinv-scaled)
    }
    int s = g_rowptr[w], e = g_rowptr[w + 1];
    for (int i = s; i < e; i++) {
        int u = g_col[i];
        const float* hu = hs + (size_t)u * D;
        #pragma unroll
        for (int j = 0; j < 4; j++) {
            int f = j * 32 + lane;
            if (f < D) acc[j] += __ldg(&hu[f]);
        }
    }
    float dv = g_dinv[w];
    #pragma unroll
    for (int j = 0; j < 4; j++) {
        int f = j * 32 + lane;
        if (f < D) {
            float r = acc[j] * dv + __ldg(&bias[f]);
            if (relu) r = fmaxf(r, 0.f);
            out[(size_t)w * D + f] = r;
        }
    }
}

// ---------------- host launcher ----------------
extern "C" void kernel_launch(void* const* d_in, const int* in_sizes, int n_in,
                              void* d_out, int out_size) {
    const float* x    = (const float*)d_in[0];
    const int*   ei   = (const int*)d_in[1];
    const float* W1   = (const float*)d_in[2];
    const float* b1   = (const float*)d_in[3];
    const float* W2   = (const float*)d_in[4];
    const float* b2   = (const float*)d_in[5];
    const float* W3   = (const float*)d_in[6];
    const float* b3   = (const float*)d_in[7];
    float* out = (float*)d_out;

    int hid   = in_sizes[3];                 // 64
    int odim  = in_sizes[7];                 // 112
    int indim = in_sizes[2] / hid;           // 128
    int n     = in_sizes[0] / indim;         // 100000
    int e     = in_sizes[1] / 2;             // 1600000
    const int* src = ei;
    const int* dst = ei + e;

    float *hs_p, *ag_p;
    cudaGetSymbolAddress((void**)&hs_p, g_hs);
    cudaGetSymbolAddress((void**)&ag_p, g_ag);

    // --- build CSR + dinv (depends only on edge_index; rebuilt every call) ---
    zero_kernel<<<(n + 255) / 256, 256>>>(n);
    hist_kernel<<<(e + 255) / 256, 256>>>(dst, e);
    scan_kernel<<<1, 1024>>>(n);
    dinv_kernel<<<(n + 255) / 256, 256>>>(n);
    scatter_kernel<<<(e + 255) / 256, 256>>>(src, dst, e);

    dim3 gblk(256);
    int aggBlocks = (n * 32 + 255) / 256;

    // layer 1: x[n,128] @ W1[128,64] -> hs ; agg -> ag (relu)
    {
        dim3 grid((hid + BN - 1) / BN, (n + BM - 1) / BM);
        gemm_scale_kernel<<<grid, gblk>>>(x, W1, hs_p, n, indim, hid);
        agg_kernel<<<aggBlocks, 256>>>(hs_p, b1, ag_p, n, hid, 1);
    }
    // layer 2: ag[n,64] @ W2[64,64] -> hs ; agg -> ag (relu)
    {
        dim3 grid((hid + BN - 1) / BN, (n + BM - 1) / BM);
        gemm_scale_kernel<<<grid, gblk>>>(ag_p, W2, hs_p, n, hid, hid);
        agg_kernel<<<aggBlocks, 256>>>(hs_p, b2, ag_p, n, hid, 1);
    }
    // layer 3: ag[n,64] @ W3[64,112] -> hs ; agg -> d_out (no relu)
    {
        dim3 grid((odim + BN - 1) / BN, (n + BM - 1) / BM);
        gemm_scale_kernel<<<grid, gblk>>>(ag_p, W3, hs_p, n, hid, odim);
        agg_kernel<<<aggBlocks, 256>>>(hs_p, b3, out, n, odim, 0);
    }
}

// round 2
// speedup vs baseline: 1.4921x; 1.4921x over previous
#include <cuda_runtime.h>
#include <cuda_bf16.h>
#include <math.h>

#define NN 100000
#define EE 1600000
#define NB_MAX 128   // ceil(NN/1024) = 98

// ---------------- device scratch ----------------
__device__ int   g_cnt[NN];
__device__ int   g_cursor[NN];
__device__ int   g_rowptr[NN + 1];
__device__ int   g_col[EE];
__device__ int   g_bsum[NB_MAX];
__device__ int   g_boff[NB_MAX];
__device__ float g_dinv[NN];
__device__ float g_hs[(size_t)NN * 64];   // ping
__device__ float g_ag[(size_t)NN * 64];   // pong

// ---------------- preprocessing ----------------
__global__ void zero_kernel(int n) {
    int i = blockIdx.x * blockDim.x + threadIdx.x;
    if (i < n) { g_cnt[i] = 0; g_cursor[i] = 0; }
}

__global__ void hist_kernel(const int* __restrict__ dst, int e) {
    int i = blockIdx.x * blockDim.x + threadIdx.x;
    if (i < e) atomicAdd(&g_cnt[__ldg(&dst[i])], 1);
}

// pass 1: per-block (1024-wide) exclusive scan, block sums to g_bsum
__global__ void scan_blocks(int n) {
    __shared__ int wsum[32];
    int tid = threadIdx.x;
    int lane = tid & 31, wid = tid >> 5;
    int gid = blockIdx.x * 1024 + tid;
    int v = (gid < n) ? g_cnt[gid] : 0;
    int x = v;
    #pragma unroll
    for (int off = 1; off < 32; off <<= 1) {
        int t = __shfl_up_sync(0xffffffffu, x, off);
        if (lane >= off) x += t;
    }
    if (lane == 31) wsum[wid] = x;
    __syncthreads();
    if (wid == 0) {
        int s = wsum[lane];
        #pragma unroll
        for (int off = 1; off < 32; off <<= 1) {
            int t = __shfl_up_sync(0xffffffffu, s, off);
            if (lane >= off) s += t;
        }
        wsum[lane] = s;
    }
    __syncthreads();
    int incl = x + (wid > 0 ? wsum[wid - 1] : 0);
    if (gid < n) g_rowptr[gid] = incl - v;   // local exclusive
    if (tid == 1023) g_bsum[blockIdx.x] = incl;
}

// pass 2: scan the (<=128) block sums
__global__ void scan_partials(int nb, int n) {
    __shared__ int wsum[4];
    int tid = threadIdx.x;        // 128 threads
    int lane = tid & 31, wid = tid >> 5;
    int v = (tid < nb) ? g_bsum[tid] : 0;
    int x = v;
    #pragma unroll
    for (int off = 1; off < 32; off <<= 1) {
        int t = __shfl_up_sync(0xffffffffu, x, off);
        if (lane >= off) x += t;
    }
    if (lane == 31) wsum[wid] = x;
    __syncthreads();
    int add = 0;
    for (int w = 0; w < wid; w++) add += wsum[w];
    int incl = x + add;
    if (tid < nb) g_boff[tid] = incl - v;    // exclusive
    if (tid == nb - 1) g_rowptr[n] = incl;   // total = e
}

// pass 3: add block offsets + compute dinv
__global__ void finalize_kernel(int n) {
    int i = blockIdx.x * blockDim.x + threadIdx.x;
    if (i < n) {
        g_rowptr[i] += g_boff[i >> 10];
        g_dinv[i] = rsqrtf((float)(g_cnt[i] + 1));
    }
}

__global__ void scatter_kernel(const int* __restrict__ src,
                               const int* __restrict__ dst, int e) {
    int i = blockIdx.x * blockDim.x + threadIdx.x;
    if (i < e) {
        int d = __ldg(&dst[i]);
        int pos = g_rowptr[d] + atomicAdd(&g_cursor[d], 1);
        g_col[pos] = __ldg(&src[i]);
    }
}

// ---------------- GEMM: out[r,c] = (sum_k X[r,k] W[k,c]) * rowscale?[r] + bias?[c] ----------------
#define BM 64
#define BN 64
#define BK 32
__global__ void gemm_kernel(const float* __restrict__ X,
                            const float* __restrict__ W,
                            float* __restrict__ out,
                            int M, int K, int Nn,
                            const float* __restrict__ rowscale,
                            const float* __restrict__ bias) {
    __shared__ float Xs[BM][BK + 1];
    __shared__ float Ws[BK][BN];
    int tid = threadIdx.x;
    int rowbase = blockIdx.y * BM;
    int colbase = blockIdx.x * BN;
    int tcol = tid & 15;
    int trow = tid >> 4;
    float acc[4][4] = {};
    for (int kb = 0; kb < K; kb += BK) {
        // X tile: 64x32 scalars, coalesced
        #pragma unroll
        for (int l = 0; l < 8; l++) {
            int idx = l * 256 + tid;
            int r = idx >> 5, c = idx & 31;
            int gr = rowbase + r;
            Xs[r][c] = (gr < M) ? __ldg(&X[(size_t)gr * K + kb + c]) : 0.f;
        }
        // W tile: 32x64 as float4
        #pragma unroll
        for (int l = 0; l < 2; l++) {
            int idx = l * 256 + tid;
            int r = idx >> 4, c4 = idx & 15;
            int gc = colbase + c4 * 4;
            float4 wv = make_float4(0.f, 0.f, 0.f, 0.f);
            if (gc + 3 < Nn)
                wv = *reinterpret_cast<const float4*>(&W[(size_t)(kb + r) * Nn + gc]);
            *reinterpret_cast<float4*>(&Ws[r][c4 * 4]) = wv;
        }
        __syncthreads();
        #pragma unroll
        for (int k = 0; k < BK; k++) {
            float a[4];
            #pragma unroll
            for (int i = 0; i < 4; i++) a[i] = Xs[trow * 4 + i][k];
            float4 bv = *reinterpret_cast<const float4*>(&Ws[k][tcol * 4]);
            float b[4] = {bv.x, bv.y, bv.z, bv.w};
            #pragma unroll
            for (int i = 0; i < 4; i++)
                #pragma unroll
                for (int j = 0; j < 4; j++)
                    acc[i][j] = fmaf(a[i], b[j], acc[i][j]);
        }
        __syncthreads();
    }
    #pragma unroll
    for (int i = 0; i < 4; i++) {
        int gr = rowbase + trow * 4 + i;
        if (gr >= M) continue;
        float rs = rowscale ? g_dinv[gr] : 1.f;
        #pragma unroll
        for (int j = 0; j < 4; j++) {
            int gc = colbase + tcol * 4 + j;
            if (gc < Nn) {
                float v = acc[i][j] * rs;
                if (bias) v += __ldg(&bias[gc]);
                out[(size_t)gr * Nn + gc] = v;
            }
        }
    }
}

// ---------------- aggregation, D=64 fixed, float4, 2 edges per warp-iter ----------------
// out[v] = dinv[v] * ( sum_u in N(v) in[u]*(scale_in?dinv[u]:1) + in[v]*(scale_in?dinv[v]:1) ) + bias? , relu?
__global__ void agg64_kernel(const float* __restrict__ hs,
                             const float* __restrict__ bias,
                             float* __restrict__ out,
                             int n, int relu, int scale_in) {
    int w = (blockIdx.x * blockDim.x + threadIdx.x) >> 5;
    if (w >= n) return;
    int lane = threadIdx.x & 31;
    int half = lane >> 4;
    int q = lane & 15;
    const float4* hs4 = (const float4*)hs;
    float ax = 0.f, ay = 0.f, az = 0.f, aw = 0.f;
    int s = g_rowptr[w], e = g_rowptr[w + 1];
    #pragma unroll 2
    for (int i = s + half; i < e; i += 2) {
        int u = __ldg(&g_col[i]);
        float4 v = __ldg(&hs4[u * 16 + q]);
        if (scale_in) {
            float dv = __ldg(&g_dinv[u]);
            v.x *= dv; v.y *= dv; v.z *= dv; v.w *= dv;
        }
        ax += v.x; ay += v.y; az += v.z; aw += v.w;
    }
    // combine the two halves
    ax += __shfl_xor_sync(0xffffffffu, ax, 16);
    ay += __shfl_xor_sync(0xffffffffu, ay, 16);
    az += __shfl_xor_sync(0xffffffffu, az, 16);
    aw += __shfl_xor_sync(0xffffffffu, aw, 16);
    // self-loop
    float4 sv = __ldg(&hs4[w * 16 + q]);
    float dv = g_dinv[w];
    float si = scale_in ? dv : 1.f;
    ax += sv.x * si; ay += sv.y * si; az += sv.z * si; aw += sv.w * si;
    ax *= dv; ay *= dv; az *= dv; aw *= dv;
    if (bias) {
        float4 bv = __ldg(&((const float4*)bias)[q]);
        ax += bv.x; ay += bv.y; az += bv.z; aw += bv.w;
    }
    if (relu) {
        ax = fmaxf(ax, 0.f); ay = fmaxf(ay, 0.f);
        az = fmaxf(az, 0.f); aw = fmaxf(aw, 0.f);
    }
    if (lane < 16) {
        ((float4*)out)[w * 16 + q] = make_float4(ax, ay, az, aw);
    }
}

// ---------------- host launcher ----------------
extern "C" void kernel_launch(void* const* d_in, const int* in_sizes, int n_in,
                              void* d_out, int out_size) {
    const float* x  = (const float*)d_in[0];
    const int*   ei = (const int*)d_in[1];
    const float* W1 = (const float*)d_in[2];
    const float* b1 = (const float*)d_in[3];
    const float* W2 = (const float*)d_in[4];
    const float* b2 = (const float*)d_in[5];
    const float* W3 = (const float*)d_in[6];
    const float* b3 = (const float*)d_in[7];
    float* out = (float*)d_out;

    int hid   = in_sizes[3];            // 64
    int odim  = in_sizes[7];            // 112
    int indim = in_sizes[2] / hid;      // 128
    int n     = in_sizes[0] / indim;    // 100000
    int e     = in_sizes[1] / 2;        // 1600000
    const int* src = ei;
    const int* dst = ei + e;

    float *hs_p, *ag_p;
    cudaGetSymbolAddress((void**)&hs_p, g_hs);
    cudaGetSymbolAddress((void**)&ag_p, g_ag);

    int nb = (n + 1023) / 1024;

    // CSR + dinv
    zero_kernel<<<(n + 255) / 256, 256>>>(n);
    hist_kernel<<<(e + 255) / 256, 256>>>(dst, e);
    scan_blocks<<<nb, 1024>>>(n);
    scan_partials<<<1, 128>>>(nb, n);
    finalize_kernel<<<(n + 255) / 256, 256>>>(n);
    scatter_kernel<<<(e + 255) / 256, 256>>>(src, dst, e);

    int aggBlocks = (n * 32 + 255) / 256;
    int gy = (n + BM - 1) / BM;

    // layer 1: GEMM x@W1 (dinv-scaled rows) -> hs ; agg(+b1, relu) -> ag
    gemm_kernel<<<dim3(1, gy), 256>>>(x, W1, hs_p, n, indim, hid, g_dinv, nullptr);
    agg64_kernel<<<aggBlocks, 256>>>(hs_p, b1, ag_p, n, 1, 0);

    // layer 2: GEMM ag@W2 (dinv-scaled rows) -> hs ; agg(+b2, relu) -> ag
    gemm_kernel<<<dim3(1, gy), 256>>>(ag_p, W2, hs_p, n, hid, hid, g_dinv, nullptr);
    agg64_kernel<<<aggBlocks, 256>>>(hs_p, b2, ag_p, n, 1, 0);

    // layer 3 (reordered): agg(ag, input-scaled by dinv) -> hs ; GEMM hs@W3 + b3 -> out
    agg64_kernel<<<aggBlocks, 256>>>(ag_p, nullptr, hs_p, n, 0, 1);
    gemm_kernel<<<dim3((odim + BN - 1) / BN, gy), 256>>>(hs_p, W3, out, n, hid, odim,
                                                         nullptr, b3);
}

// round 4
// speedup vs baseline: 1.8837x; 1.2624x over previous
#include <cuda_runtime.h>
#include <cuda_bf16.h>
#include <math.h>
#include <stdint.h>

#define NN 100000
#define EE 1600000
#define NB_MAX 128

// ---------------- device scratch ----------------
__device__ int   g_cnt[NN];
__device__ int   g_cursor[NN];
__device__ int   g_rowptr[NN + 1];
__device__ int   g_col[EE];
__device__ int   g_bsum[NB_MAX];
__device__ int   g_boff[NB_MAX];
__device__ float g_dinv[NN];
__device__ float g_hs[(size_t)NN * 64];
__device__ float g_ag[(size_t)NN * 64];

// ---------------- preprocessing ----------------
__global__ void zero_kernel(int n) {
    int i = blockIdx.x * blockDim.x + threadIdx.x;
    if (i < n) { g_cnt[i] = 0; g_cursor[i] = 0; }
}
__global__ void hist_kernel(const int* __restrict__ dst, int e) {
    int i = blockIdx.x * blockDim.x + threadIdx.x;
    if (i < e) atomicAdd(&g_cnt[__ldg(&dst[i])], 1);
}
__global__ void scan_blocks(int n) {
    __shared__ int wsum[32];
    int tid = threadIdx.x, lane = tid & 31, wid = tid >> 5;
    int gid = blockIdx.x * 1024 + tid;
    int v = (gid < n) ? g_cnt[gid] : 0;
    int x = v;
    #pragma unroll
    for (int off = 1; off < 32; off <<= 1) {
        int t = __shfl_up_sync(0xffffffffu, x, off);
        if (lane >= off) x += t;
    }
    if (lane == 31) wsum[wid] = x;
    __syncthreads();
    if (wid == 0) {
        int s = wsum[lane];
        #pragma unroll
        for (int off = 1; off < 32; off <<= 1) {
            int t = __shfl_up_sync(0xffffffffu, s, off);
            if (lane >= off) s += t;
        }
        wsum[lane] = s;
    }
    __syncthreads();
    int incl = x + (wid > 0 ? wsum[wid - 1] : 0);
    if (gid < n) g_rowptr[gid] = incl - v;
    if (tid == 1023) g_bsum[blockIdx.x] = incl;
}
__global__ void scan_partials(int nb, int n) {
    __shared__ int wsum[4];
    int tid = threadIdx.x, lane = tid & 31, wid = tid >> 5;
    int v = (tid < nb) ? g_bsum[tid] : 0;
    int x = v;
    #pragma unroll
    for (int off = 1; off < 32; off <<= 1) {
        int t = __shfl_up_sync(0xffffffffu, x, off);
        if (lane >= off) x += t;
    }
    if (lane == 31) wsum[wid] = x;
    __syncthreads();
    int add = 0;
    for (int w = 0; w < wid; w++) add += wsum[w];
    int incl = x + add;
    if (tid < nb) g_boff[tid] = incl - v;
    if (tid == nb - 1) g_rowptr[n] = incl;
}
__global__ void finalize_kernel(int n) {
    int i = blockIdx.x * blockDim.x + threadIdx.x;
    if (i < n) {
        g_rowptr[i] += g_boff[i >> 10];
        g_dinv[i] = rsqrtf((float)(g_cnt[i] + 1));
    }
}
__global__ void scatter_kernel(const int* __restrict__ src,
                               const int* __restrict__ dst, int e) {
    int i = blockIdx.x * blockDim.x + threadIdx.x;
    if (i < e) {
        int d = __ldg(&dst[i]);
        int pos = g_rowptr[d] + atomicAdd(&g_cursor[d], 1);
        g_col[pos] = __ldg(&src[i]);
    }
}

// ---------------- mma.sync bf16 helpers ----------------
__device__ __forceinline__ uint32_t pack_bf2(float a, float b) {
    __nv_bfloat162 t = __floats2bfloat162_rn(a, b);
    return *reinterpret_cast<uint32_t*>(&t);
}
__device__ __forceinline__ void mma_bf16(float* c, uint32_t a0, uint32_t a1,
                                         uint32_t a2, uint32_t a3,
                                         uint32_t b0, uint32_t b1) {
    asm volatile(
        "mma.sync.aligned.m16n8k16.row.col.f32.bf16.bf16.f32 "
        "{%0,%1,%2,%3}, {%4,%5,%6,%7}, {%8,%9}, {%0,%1,%2,%3};"
        : "+f"(c[0]), "+f"(c[1]), "+f"(c[2]), "+f"(c[3])
        : "r"(a0), "r"(a1), "r"(a2), "r"(a3), "r"(b0), "r"(b1));
}

// ---------------- tensor-core GEMM via mma.sync (bf16 3-pass split) ----------------
// out[r,c] = (sum_k X[r,k] W[k,c]) * (use_rowscale? dinv[r]:1) + bias?[c]
// CTA: 128 threads, M-tile 64; warp: 16 rows x N. K = KS*16, N = NT*8.
template <int KS, int NT>
__global__ void __launch_bounds__(128)
gemm_mma_kernel(const float* __restrict__ X, const float* __restrict__ W,
                float* __restrict__ out, int M,
                int use_rowscale, const float* __restrict__ bias) {
    constexpr int K  = KS * 16;
    constexpr int Nn = NT * 8;
    constexpr int PA = K + 2;   // padded pitch (bf16 elems)
    extern __shared__ __nv_bfloat16 sm[];
    __nv_bfloat16* aHi = sm;
    __nv_bfloat16* aLo = aHi + 64 * PA;
    __nv_bfloat16* wHi = aLo + 64 * PA;
    __nv_bfloat16* wLo = wHi + Nn * PA;

    int tid = threadIdx.x, lane = tid & 31, wid = tid >> 5;
    int rowbase = blockIdx.x * 64;

    // ---- A tile fill: fp32 -> (hi, lo) bf16, row-major padded ----
    #pragma unroll
    for (int idx = tid; idx < 64 * (K / 4); idx += 128) {
        int r = idx / (K / 4);
        int c = (idx % (K / 4)) * 4;
        float4 v = make_float4(0.f, 0.f, 0.f, 0.f);
        int gr = rowbase + r;
        if (gr < M) v = __ldg((const float4*)(X + (size_t)gr * K + c));
        float hx = __bfloat162float(__float2bfloat16(v.x));
        float hy = __bfloat162float(__float2bfloat16(v.y));
        float hz = __bfloat162float(__float2bfloat16(v.z));
        float hw = __bfloat162float(__float2bfloat16(v.w));
        int o = r * PA + c;   // even -> 4B aligned
        *(uint32_t*)(aHi + o)     = pack_bf2(v.x, v.y);
        *(uint32_t*)(aHi + o + 2) = pack_bf2(v.z, v.w);
        *(uint32_t*)(aLo + o)     = pack_bf2(v.x - hx, v.y - hy);
        *(uint32_t*)(aLo + o + 2) = pack_bf2(v.z - hz, v.w - hw);
    }
    // ---- W tile fill: transpose to Wt[n][k], hi/lo ----
    #pragma unroll
    for (int idx = tid; idx < K * Nn; idx += 128) {
        int k = idx / Nn, n2 = idx - k * Nn;
        float v = __ldg(&W[idx]);
        __nv_bfloat16 h = __float2bfloat16(v);
        __nv_bfloat16 l = __float2bfloat16(v - __bfloat162float(h));
        wHi[n2 * PA + k] = h;
        wLo[n2 * PA + k] = l;
    }
    __syncthreads();

    int gp = lane >> 2;       // 0..7
    int tig = lane & 3;       // 0..3
    int ar0 = (wid * 16 + gp) * PA + tig * 2;        // row gp
    int ar1 = ar0 + 8 * PA;                          // row gp+8

    float acc[NT][4];
    #pragma unroll
    for (int t = 0; t < NT; t++) {
        acc[t][0] = 0.f; acc[t][1] = 0.f; acc[t][2] = 0.f; acc[t][3] = 0.f;
    }

    #pragma unroll
    for (int pass = 0; pass < 3; pass++) {
        const __nv_bfloat16* aB = (pass == 2) ? aLo : aHi;
        const __nv_bfloat16* wB = (pass == 1) ? wLo : wHi;
        #pragma unroll
        for (int kt = 0; kt < KS; kt++) {
            int ko = kt * 16;
            uint32_t a0 = *(const uint32_t*)(aB + ar0 + ko);
            uint32_t a1 = *(const uint32_t*)(aB + ar1 + ko);
            uint32_t a2 = *(const uint32_t*)(aB + ar0 + ko + 8);
            uint32_t a3 = *(const uint32_t*)(aB + ar1 + ko + 8);
            #pragma unroll
            for (int nt = 0; nt < NT; nt++) {
                const __nv_bfloat16* wp = wB + (nt * 8 + gp) * PA + ko + tig * 2;
                uint32_t b0 = *(const uint32_t*)(wp);
                uint32_t b1 = *(const uint32_t*)(wp + 8);
                mma_bf16(acc[nt], a0, a1, a2, a3, b0, b1);
            }
        }
    }

    // ---- epilogue: C frag (m16n8): rows gp, gp+8; cols tig*2, tig*2+1 ----
    int r0 = rowbase + wid * 16 + gp;
    int r1 = r0 + 8;
    float rs0 = 1.f, rs1 = 1.f;
    if (use_rowscale) {
        if (r0 < M) rs0 = __ldg(&g_dinv[r0]);
        if (r1 < M) rs1 = __ldg(&g_dinv[r1]);
    }
    #pragma unroll
    for (int nt = 0; nt < NT; nt++) {
        int col = nt * 8 + tig * 2;
        float bx = 0.f, by = 0.f;
        if (bias) {
            float2 bv = __ldg((const float2*)&bias[col]);
            bx = bv.x; by = bv.y;
        }
        if (r0 < M) {
            float2 v = make_float2(acc[nt][0] * rs0 + bx, acc[nt][1] * rs0 + by);
            *(float2*)(out + (size_t)r0 * Nn + col) = v;
        }
        if (r1 < M) {
            float2 v = make_float2(acc[nt][2] * rs1 + bx, acc[nt][3] * rs1 + by);
            *(float2*)(out + (size_t)r1 * Nn + col) = v;
        }
    }
}

// ---------------- aggregation (unchanged) ----------------
__global__ void agg64_kernel(const float* __restrict__ hs,
                             const float* __restrict__ bias,
                             float* __restrict__ out,
                             int n, int relu, int scale_in) {
    int w = (blockIdx.x * blockDim.x + threadIdx.x) >> 5;
    if (w >= n) return;
    int lane = threadIdx.x & 31;
    int half = lane >> 4;
    int q = lane & 15;
    const float4* hs4 = (const float4*)hs;
    float ax = 0.f, ay = 0.f, az = 0.f, aw = 0.f;
    int s = g_rowptr[w], e = g_rowptr[w + 1];
    #pragma unroll 2
    for (int i = s + half; i < e; i += 2) {
        int u = __ldg(&g_col[i]);
        float4 v = __ldg(&hs4[u * 16 + q]);
        if (scale_in) {
            float dv = __ldg(&g_dinv[u]);
            v.x *= dv; v.y *= dv; v.z *= dv; v.w *= dv;
        }
        ax += v.x; ay += v.y; az += v.z; aw += v.w;
    }
    ax += __shfl_xor_sync(0xffffffffu, ax, 16);
    ay += __shfl_xor_sync(0xffffffffu, ay, 16);
    az += __shfl_xor_sync(0xffffffffu, az, 16);
    aw += __shfl_xor_sync(0xffffffffu, aw, 16);
    float4 sv = __ldg(&hs4[w * 16 + q]);
    float dv = g_dinv[w];
    float si = scale_in ? dv : 1.f;
    ax += sv.x * si; ay += sv.y * si; az += sv.z * si; aw += sv.w * si;
    ax *= dv; ay *= dv; az *= dv; aw *= dv;
    if (bias) {
        float4 bv = __ldg(&((const float4*)bias)[q]);
        ax += bv.x; ay += bv.y; az += bv.z; aw += bv.w;
    }
    if (relu) {
        ax = fmaxf(ax, 0.f); ay = fmaxf(ay, 0.f);
        az = fmaxf(az, 0.f); aw = fmaxf(aw, 0.f);
    }
    if (lane < 16) ((float4*)out)[w * 16 + q] = make_float4(ax, ay, az, aw);
}

// ---------------- host launcher ----------------
extern "C" void kernel_launch(void* const* d_in, const int* in_sizes, int n_in,
                              void* d_out, int out_size) {
    const float* x  = (const float*)d_in[0];
    const int*   ei = (const int*)d_in[1];
    const float* W1 = (const float*)d_in[2];
    const float* b1 = (const float*)d_in[3];
    const float* W2 = (const float*)d_in[4];
    const float* b2 = (const float*)d_in[5];
    const float* W3 = (const float*)d_in[6];
    const float* b3 = (const float*)d_in[7];
    float* out = (float*)d_out;

    int hid   = in_sizes[3];            // 64
    int odim  = in_sizes[7];            // 112
    int indim = in_sizes[2] / hid;      // 128
    int n     = in_sizes[0] / indim;    // 100000
    int e     = in_sizes[1] / 2;        // 1600000
    const int* src = ei;
    const int* dst = ei + e;

    float *hs_p, *ag_p;
    cudaGetSymbolAddress((void**)&hs_p, g_hs);
    cudaGetSymbolAddress((void**)&ag_p, g_ag);

    int nb = (n + 1023) / 1024;
    zero_kernel<<<(n + 255) / 256, 256>>>(n);
    hist_kernel<<<(e + 255) / 256, 256>>>(dst, e);
    scan_blocks<<<nb, 1024>>>(n);
    scan_partials<<<1, 128>>>(nb, n);
    finalize_kernel<<<(n + 255) / 256, 256>>>(n);
    scatter_kernel<<<(e + 255) / 256, 256>>>(src, dst, e);

    int aggBlocks = (n * 32 + 255) / 256;
    int gGrid = (n + 63) / 64;

    // dynamic smem: (64 + Nn) * (K+2) * 2 bf16 * 2 bytes
    auto smem_sz = [](int K, int Nn) { return (64 + Nn) * (K + 2) * 2 * 2; };
    cudaFuncSetAttribute(gemm_mma_kernel<8, 8>,
                         cudaFuncAttributeMaxDynamicSharedMemorySize, smem_sz(128, 64));
    cudaFuncSetAttribute(gemm_mma_kernel<4, 8>,
                         cudaFuncAttributeMaxDynamicSharedMemorySize, smem_sz(64, 64));
    cudaFuncSetAttribute(gemm_mma_kernel<4, 14>,
                         cudaFuncAttributeMaxDynamicSharedMemorySize, smem_sz(64, 112));

    // layer 1: x[n,128]@W1 -> hs (rowscaled); agg(+b1, relu) -> ag
    gemm_mma_kernel<8, 8><<<gGrid, 128, smem_sz(128, 64)>>>(x, W1, hs_p, n, 1, nullptr);
    agg64_kernel<<<aggBlocks, 256>>>(hs_p, b1, ag_p, n, 1, 0);
    // layer 2
    gemm_mma_kernel<4, 8><<<gGrid, 128, smem_sz(64, 64)>>>(ag_p, W2, hs_p, n, 1, nullptr);
    agg64_kernel<<<aggBlocks, 256>>>(hs_p, b2, ag_p, n, 1, 0);
    // layer 3: agg first (input-scaled), then GEMM to 112 with bias
    agg64_kernel<<<aggBlocks, 256>>>(ag_p, nullptr, hs_p, n, 0, 1);
    gemm_mma_kernel<4, 14><<<gGrid, 128, smem_sz(64, 112)>>>(hs_p, W3, out, n, 0, b3);
}

// round 5
// speedup vs baseline: 2.0218x; 1.0733x over previous
#include <cuda_runtime.h>
#include <cuda_bf16.h>
#include <math.h>
#include <stdint.h>

#define NN 100000
#define EE 1600000
#define NB_MAX 128

// ---------------- device scratch ----------------
__device__ int   g_cnt[NN];
__device__ int   g_cursor[NN];
__device__ int   g_rowptr[NN + 1];
__device__ int   g_col[EE];
__device__ int   g_bsum[NB_MAX];
__device__ int   g_boff[NB_MAX];
__device__ float g_dinv[NN];
__device__ float g_hs[(size_t)NN * 64];
__device__ float g_ag[(size_t)NN * 64];

// ---------------- preprocessing ----------------
__global__ void zero_kernel(int n) {
    int i = blockIdx.x * blockDim.x + threadIdx.x;
    if (i < n) { g_cnt[i] = 0; g_cursor[i] = 0; }
}
__global__ void hist_kernel(const int* __restrict__ dst, int e) {
    int i = blockIdx.x * blockDim.x + threadIdx.x;
    if (i < e) atomicAdd(&g_cnt[__ldg(&dst[i])], 1);
}
__global__ void scan_blocks(int n) {
    __shared__ int wsum[32];
    int tid = threadIdx.x, lane = tid & 31, wid = tid >> 5;
    int gid = blockIdx.x * 1024 + tid;
    int v = (gid < n) ? g_cnt[gid] : 0;
    int x = v;
    #pragma unroll
    for (int off = 1; off < 32; off <<= 1) {
        int t = __shfl_up_sync(0xffffffffu, x, off);
        if (lane >= off) x += t;
    }
    if (lane == 31) wsum[wid] = x;
    __syncthreads();
    if (wid == 0) {
        int s = wsum[lane];
        #pragma unroll
        for (int off = 1; off < 32; off <<= 1) {
            int t = __shfl_up_sync(0xffffffffu, s, off);
            if (lane >= off) s += t;
        }
        wsum[lane] = s;
    }
    __syncthreads();
    int incl = x + (wid > 0 ? wsum[wid - 1] : 0);
    if (gid < n) g_rowptr[gid] = incl - v;
    if (tid == 1023) g_bsum[blockIdx.x] = incl;
}
__global__ void scan_partials(int nb, int n) {
    __shared__ int wsum[4];
    int tid = threadIdx.x, lane = tid & 31, wid = tid >> 5;
    int v = (tid < nb) ? g_bsum[tid] : 0;
    int x = v;
    #pragma unroll
    for (int off = 1; off < 32; off <<= 1) {
        int t = __shfl_up_sync(0xffffffffu, x, off);
        if (lane >= off) x += t;
    }
    if (lane == 31) wsum[wid] = x;
    __syncthreads();
    int add = 0;
    for (int w = 0; w < wid; w++) add += wsum[w];
    int incl = x + add;
    if (tid < nb) g_boff[tid] = incl - v;
    if (tid == nb - 1) g_rowptr[n] = incl;
}
__global__ void finalize_kernel(int n) {
    int i = blockIdx.x * blockDim.x + threadIdx.x;
    if (i < n) {
        g_rowptr[i] += g_boff[i >> 10];
        g_dinv[i] = rsqrtf((float)(g_cnt[i] + 1));
    }
}
__global__ void scatter_kernel(const int* __restrict__ src,
                               const int* __restrict__ dst, int e) {
    int i = blockIdx.x * blockDim.x + threadIdx.x;
    if (i < e) {
        int d = __ldg(&dst[i]);
        int pos = g_rowptr[d] + atomicAdd(&g_cursor[d], 1);
        g_col[pos] = __ldg(&src[i]);
    }
}

// ---------------- mma.sync bf16 helpers ----------------
__device__ __forceinline__ uint32_t pack_bf2(float a, float b) {
    __nv_bfloat162 t = __floats2bfloat162_rn(a, b);
    return *reinterpret_cast<uint32_t*>(&t);
}
__device__ __forceinline__ void mma_bf16(float* c, uint32_t a0, uint32_t a1,
                                         uint32_t a2, uint32_t a3,
                                         uint32_t b0, uint32_t b1) {
    asm volatile(
        "mma.sync.aligned.m16n8k16.row.col.f32.bf16.bf16.f32 "
        "{%0,%1,%2,%3}, {%4,%5,%6,%7}, {%8,%9}, {%0,%1,%2,%3};"
        : "+f"(c[0]), "+f"(c[1]), "+f"(c[2]), "+f"(c[3])
        : "r"(a0), "r"(a1), "r"(a2), "r"(a3), "r"(b0), "r"(b1));
}

// ---------------- GEMM via mma.sync, bf16 3-term split with fragment reuse ----
// out[r,c] = sum_k X[r,k] W[k,c] + bias?[c]
// CTA: 256 threads / 8 warps, M-tile 128; warp: 16 rows x N. K=KS*16, N=NT*8.
template <int KS, int NT>
__global__ void __launch_bounds__(256)
gemm_mma_kernel(const float* __restrict__ X, const float* __restrict__ W,
                float* __restrict__ out, int M, const float* __restrict__ bias) {
    constexpr int K  = KS * 16;
    constexpr int Nn = NT * 8;
    constexpr int PA = K + 2;
    extern __shared__ __nv_bfloat16 sm[];
    __nv_bfloat16* aHi = sm;
    __nv_bfloat16* aLo = aHi + 128 * PA;
    __nv_bfloat16* wHi = aLo + 128 * PA;
    __nv_bfloat16* wLo = wHi + Nn * PA;

    int tid = threadIdx.x, lane = tid & 31, wid = tid >> 5;
    int rowbase = blockIdx.x * 128;

    // ---- A tile fill: fp32 -> (hi, lo) bf16 ----
    #pragma unroll
    for (int idx = tid; idx < 128 * (K / 4); idx += 256) {
        int r = idx / (K / 4);
        int c = (idx % (K / 4)) * 4;
        float4 v = make_float4(0.f, 0.f, 0.f, 0.f);
        int gr = rowbase + r;
        if (gr < M) v = __ldg((const float4*)(X + (size_t)gr * K + c));
        float hx = __bfloat162float(__float2bfloat16(v.x));
        float hy = __bfloat162float(__float2bfloat16(v.y));
        float hz = __bfloat162float(__float2bfloat16(v.z));
        float hw = __bfloat162float(__float2bfloat16(v.w));
        int o = r * PA + c;
        *(uint32_t*)(aHi + o)     = pack_bf2(v.x, v.y);
        *(uint32_t*)(aHi + o + 2) = pack_bf2(v.z, v.w);
        *(uint32_t*)(aLo + o)     = pack_bf2(v.x - hx, v.y - hy);
        *(uint32_t*)(aLo + o + 2) = pack_bf2(v.z - hz, v.w - hw);
    }
    // ---- W tile fill: transpose to Wt[n][k], hi/lo ----
    #pragma unroll
    for (int idx = tid; idx < K * Nn; idx += 256) {
        int k = idx / Nn, n2 = idx - k * Nn;
        float v = __ldg(&W[idx]);
        __nv_bfloat16 h = __float2bfloat16(v);
        __nv_bfloat16 l = __float2bfloat16(v - __bfloat162float(h));
        wHi[n2 * PA + k] = h;
        wLo[n2 * PA + k] = l;
    }
    __syncthreads();

    int gp = lane >> 2;
    int tig = lane & 3;
    int ar0 = (wid * 16 + gp) * PA + tig * 2;
    int ar1 = ar0 + 8 * PA;

    float acc[NT][4];
    #pragma unroll
    for (int t = 0; t < NT; t++) {
        acc[t][0] = 0.f; acc[t][1] = 0.f; acc[t][2] = 0.f; acc[t][3] = 0.f;
    }

    #pragma unroll
    for (int kt = 0; kt < KS; kt++) {
        int ko = kt * 16;
        uint32_t ah0 = *(const uint32_t*)(aHi + ar0 + ko);
        uint32_t ah1 = *(const uint32_t*)(aHi + ar1 + ko);
        uint32_t ah2 = *(const uint32_t*)(aHi + ar0 + ko + 8);
        uint32_t ah3 = *(const uint32_t*)(aHi + ar1 + ko + 8);
        uint32_t al0 = *(const uint32_t*)(aLo + ar0 + ko);
        uint32_t al1 = *(const uint32_t*)(aLo + ar1 + ko);
        uint32_t al2 = *(const uint32_t*)(aLo + ar0 + ko + 8);
        uint32_t al3 = *(const uint32_t*)(aLo + ar1 + ko + 8);
        #pragma unroll
        for (int nt = 0; nt < NT; nt++) {
            int wo = (nt * 8 + gp) * PA + ko + tig * 2;
            uint32_t bh0 = *(const uint32_t*)(wHi + wo);
            uint32_t bh1 = *(const uint32_t*)(wHi + wo + 8);
            uint32_t bl0 = *(const uint32_t*)(wLo + wo);
            uint32_t bl1 = *(const uint32_t*)(wLo + wo + 8);
            mma_bf16(acc[nt], ah0, ah1, ah2, ah3, bh0, bh1);
            mma_bf16(acc[nt], ah0, ah1, ah2, ah3, bl0, bl1);
            mma_bf16(acc[nt], al0, al1, al2, al3, bh0, bh1);
        }
    }

    // ---- epilogue ----
    int r0 = rowbase + wid * 16 + gp;
    int r1 = r0 + 8;
    #pragma unroll
    for (int nt = 0; nt < NT; nt++) {
        int col = nt * 8 + tig * 2;
        float bx = 0.f, by = 0.f;
        if (bias) {
            float2 bv = __ldg((const float2*)&bias[col]);
            bx = bv.x; by = bv.y;
        }
        if (r0 < M)
            *(float2*)(out + (size_t)r0 * Nn + col) =
                make_float2(acc[nt][0] + bx, acc[nt][1] + by);
        if (r1 < M)
            *(float2*)(out + (size_t)r1 * Nn + col) =
                make_float2(acc[nt][2] + bx, acc[nt][3] + by);
    }
}

// ---------------- aggregation: unified dinv form, 4 edges/warp-iter ----------------
// out[v] = dinv[v]*( sum_u dinv[u]*in[u] + dinv[v]*in[v] ) + bias?, relu?
__global__ void agg64_kernel(const float* __restrict__ hs,
                             const float* __restrict__ bias,
                             float* __restrict__ out,
                             int n, int relu) {
    int w = (blockIdx.x * blockDim.x + threadIdx.x) >> 5;
    if (w >= n) return;
    int lane = threadIdx.x & 31;
    int half = lane >> 4;
    int q = lane & 15;
    const float4* hs4 = (const float4*)hs;
    float ax = 0.f, ay = 0.f, az = 0.f, aw = 0.f;
    int s = g_rowptr[w], e = g_rowptr[w + 1];
    int i = s + half;
    for (; i + 2 < e; i += 4) {
        int u0 = __ldg(&g_col[i]);
        int u1 = __ldg(&g_col[i + 2]);
        float d0 = __ldg(&g_dinv[u0]);
        float d1 = __ldg(&g_dinv[u1]);
        float4 v0 = __ldg(&hs4[u0 * 16 + q]);
        float4 v1 = __ldg(&hs4[u1 * 16 + q]);
        ax += d0 * v0.x + d1 * v1.x;
        ay += d0 * v0.y + d1 * v1.y;
        az += d0 * v0.z + d1 * v1.z;
        aw += d0 * v0.w + d1 * v1.w;
    }
    if (i < e) {
        int u = __ldg(&g_col[i]);
        float d = __ldg(&g_dinv[u]);
        float4 v = __ldg(&hs4[u * 16 + q]);
        ax += d * v.x; ay += d * v.y; az += d * v.z; aw += d * v.w;
    }
    ax += __shfl_xor_sync(0xffffffffu, ax, 16);
    ay += __shfl_xor_sync(0xffffffffu, ay, 16);
    az += __shfl_xor_sync(0xffffffffu, az, 16);
    aw += __shfl_xor_sync(0xffffffffu, aw, 16);
    float4 sv = __ldg(&hs4[w * 16 + q]);
    float dv = __ldg(&g_dinv[w]);
    ax += sv.x * dv; ay += sv.y * dv; az += sv.z * dv; aw += sv.w * dv;
    ax *= dv; ay *= dv; az *= dv; aw *= dv;
    if (bias) {
        float4 bv = __ldg(&((const float4*)bias)[q]);
        ax += bv.x; ay += bv.y; az += bv.z; aw += bv.w;
    }
    if (relu) {
        ax = fmaxf(ax, 0.f); ay = fmaxf(ay, 0.f);
        az = fmaxf(az, 0.f); aw = fmaxf(aw, 0.f);
    }
    if (lane < 16) ((float4*)out)[w * 16 + q] = make_float4(ax, ay, az, aw);
}

// ---------------- host launcher ----------------
extern "C" void kernel_launch(void* const* d_in, const int* in_sizes, int n_in,
                              void* d_out, int out_size) {
    const float* x  = (const float*)d_in[0];
    const int*   ei = (const int*)d_in[1];
    const float* W1 = (const float*)d_in[2];
    const float* b1 = (const float*)d_in[3];
    const float* W2 = (const float*)d_in[4];
    const float* b2 = (const float*)d_in[5];
    const float* W3 = (const float*)d_in[6];
    const float* b3 = (const float*)d_in[7];
    float* out = (float*)d_out;

    int hid   = in_sizes[3];            // 64
    int odim  = in_sizes[7];            // 112
    int indim = in_sizes[2] / hid;      // 128
    int n     = in_sizes[0] / indim;    // 100000
    int e     = in_sizes[1] / 2;        // 1600000
    const int* src = ei;
    const int* dst = ei + e;

    float *hs_p, *ag_p;
    cudaGetSymbolAddress((void**)&hs_p, g_hs);
    cudaGetSymbolAddress((void**)&ag_p, g_ag);

    int nb = (n + 1023) / 1024;
    int aggBlocks = (n * 32 + 255) / 256;
    int gGrid = (n + 127) / 128;

    auto smem_sz = [](int K, int Nn) { return (128 + Nn) * (K + 2) * 2 * 2; };
    cudaFuncSetAttribute(gemm_mma_kernel<8, 8>,
                         cudaFuncAttributeMaxDynamicSharedMemorySize, smem_sz(128, 64));
    cudaFuncSetAttribute(gemm_mma_kernel<4, 8>,
                         cudaFuncAttributeMaxDynamicSharedMemorySize, smem_sz(64, 64));
    cudaFuncSetAttribute(gemm_mma_kernel<4, 14>,
                         cudaFuncAttributeMaxDynamicSharedMemorySize, smem_sz(64, 112));

    // launch index:                                                      (0-based)
    zero_kernel<<<(n + 255) / 256, 256>>>(n);                          // 0
    hist_kernel<<<(e + 255) / 256, 256>>>(dst, e);                     // 1
    scan_blocks<<<nb, 1024>>>(n);                                      // 2
    // gemm1 is CSR-independent: placed at index 3 so ncu profiles it
    gemm_mma_kernel<8, 8><<<gGrid, 256, smem_sz(128, 64)>>>(x, W1, hs_p, n, nullptr); // 3
    scan_partials<<<1, 128>>>(nb, n);                                  // 4
    finalize_kernel<<<(n + 255) / 256, 256>>>(n);                      // 5
    scatter_kernel<<<(e + 255) / 256, 256>>>(src, dst, e);             // 6

    // layer 1 aggregation (+b1, relu)
    agg64_kernel<<<aggBlocks, 256>>>(hs_p, b1, ag_p, n, 1);            // 7
    // layer 2
    gemm_mma_kernel<4, 8><<<gGrid, 256, smem_sz(64, 64)>>>(ag_p, W2, hs_p, n, nullptr);
    agg64_kernel<<<aggBlocks, 256>>>(hs_p, b2, ag_p, n, 1);
    // layer 3: agg first, then GEMM to 112 with bias
    agg64_kernel<<<aggBlocks, 256>>>(ag_p, nullptr, hs_p, n, 0);
    gemm_mma_kernel<4, 14><<<gGrid, 256, smem_sz(64, 112)>>>(hs_p, W3, out, n, b3);
}

// round 6
// speedup vs baseline: 2.4304x; 1.2021x over previous
#include <cuda_runtime.h>
#include <cuda_bf16.h>
#include <math.h>
#include <stdint.h>

#define NN 100000
#define EE 1600000
#define NB_MAX 128

// ---------------- device scratch ----------------
__device__ int   g_cnt[NN];
__device__ int   g_cursor[NN];
__device__ int   g_rowptr[NN + 1];
__device__ int   g_col[EE];
__device__ int   g_bsum[NB_MAX];
__device__ int   g_boff[NB_MAX];
__device__ float g_dinv[NN];
__device__ float g_hs[(size_t)NN * 64];
__device__ float g_ag[(size_t)NN * 64];

// ---------------- preprocessing ----------------
__global__ void zero_kernel(int n) {
    int i = blockIdx.x * blockDim.x + threadIdx.x;
    if (i < n) { g_cnt[i] = 0; g_cursor[i] = 0; }
}
__global__ void hist_kernel(const int* __restrict__ dst, int e) {
    int i = blockIdx.x * blockDim.x + threadIdx.x;
    if (i < e) atomicAdd(&g_cnt[__ldg(&dst[i])], 1);
}
__global__ void scan_blocks(int n) {
    __shared__ int wsum[32];
    int tid = threadIdx.x, lane = tid & 31, wid = tid >> 5;
    int gid = blockIdx.x * 1024 + tid;
    int v = (gid < n) ? g_cnt[gid] : 0;
    int x = v;
    #pragma unroll
    for (int off = 1; off < 32; off <<= 1) {
        int t = __shfl_up_sync(0xffffffffu, x, off);
        if (lane >= off) x += t;
    }
    if (lane == 31) wsum[wid] = x;
    __syncthreads();
    if (wid == 0) {
        int s = wsum[lane];
        #pragma unroll
        for (int off = 1; off < 32; off <<= 1) {
            int t = __shfl_up_sync(0xffffffffu, s, off);
            if (lane >= off) s += t;
        }
        wsum[lane] = s;
    }
    __syncthreads();
    int incl = x + (wid > 0 ? wsum[wid - 1] : 0);
    if (gid < n) g_rowptr[gid] = incl - v;
    if (tid == 1023) g_bsum[blockIdx.x] = incl;
}
__global__ void scan_partials(int nb, int n) {
    __shared__ int wsum[4];
    int tid = threadIdx.x, lane = tid & 31, wid = tid >> 5;
    int v = (tid < nb) ? g_bsum[tid] : 0;
    int x = v;
    #pragma unroll
    for (int off = 1; off < 32; off <<= 1) {
        int t = __shfl_up_sync(0xffffffffu, x, off);
        if (lane >= off) x += t;
    }
    if (lane == 31) wsum[wid] = x;
    __syncthreads();
    int add = 0;
    for (int w = 0; w < wid; w++) add += wsum[w];
    int incl = x + add;
    if (tid < nb) g_boff[tid] = incl - v;
    if (tid == nb - 1) g_rowptr[n] = incl;
}
__global__ void finalize_kernel(int n) {
    int i = blockIdx.x * blockDim.x + threadIdx.x;
    if (i < n) {
        g_rowptr[i] += g_boff[i >> 10];
        g_dinv[i] = rsqrtf((float)(g_cnt[i] + 1));
    }
}
__global__ void scatter_kernel(const int* __restrict__ src,
                               const int* __restrict__ dst, int e) {
    int i = blockIdx.x * blockDim.x + threadIdx.x;
    if (i < e) {
        int d = __ldg(&dst[i]);
        int pos = g_rowptr[d] + atomicAdd(&g_cursor[d], 1);
        g_col[pos] = __ldg(&src[i]);
    }
}

// ---------------- mma helpers ----------------
__device__ __forceinline__ uint32_t pack_bf2(float a, float b) {
    __nv_bfloat162 t = __floats2bfloat162_rn(a, b);
    return *reinterpret_cast<uint32_t*>(&t);
}
// lo residual of a packed-hi pair
__device__ __forceinline__ uint32_t lo_pack(float2 v, uint32_t h) {
    float hx = __uint_as_float(h << 16);
    float hy = __uint_as_float(h & 0xffff0000u);
    return pack_bf2(v.x - hx, v.y - hy);
}
__device__ __forceinline__ void mma_bf16(float* c, uint32_t a0, uint32_t a1,
                                         uint32_t a2, uint32_t a3,
                                         uint32_t b0, uint32_t b1) {
    asm volatile(
        "mma.sync.aligned.m16n8k16.row.col.f32.bf16.bf16.f32 "
        "{%0,%1,%2,%3}, {%4,%5,%6,%7}, {%8,%9}, {%0,%1,%2,%3};"
        : "+f"(c[0]), "+f"(c[1]), "+f"(c[2]), "+f"(c[3])
        : "r"(a0), "r"(a1), "r"(a2), "r"(a3), "r"(b0), "r"(b1));
}
__device__ __forceinline__ void ldsm_x4(uint32_t& r0, uint32_t& r1,
                                        uint32_t& r2, uint32_t& r3, uint32_t a) {
    asm volatile("ldmatrix.sync.aligned.m8n8.x4.shared.b16 {%0,%1,%2,%3}, [%4];"
                 : "=r"(r0), "=r"(r1), "=r"(r2), "=r"(r3) : "r"(a));
}

// ---------------- GEMM: direct-global A fragments + ldmatrix B ----------------
// out[r,c] = sum_k X[r,k] W[k,c] + bias?[c]
// CTA: 256 threads / 8 warps, M-tile 128; warp: 16 rows x full N. K=KS*16, N=NT*8.
template <int KS, int NT>
__global__ void __launch_bounds__(256)
gemm_mma_kernel(const float* __restrict__ X, const float* __restrict__ W,
                float* __restrict__ out, int M, const float* __restrict__ bias) {
    constexpr int K  = KS * 16;
    constexpr int Nn = NT * 8;
    constexpr int PA = K + 8;   // 16B-aligned rows; ldmatrix conflict-free
    extern __shared__ __nv_bfloat16 sm[];
    __nv_bfloat16* wHi = sm;
    __nv_bfloat16* wLo = wHi + Nn * PA;

    int tid = threadIdx.x, lane = tid & 31, wid = tid >> 5;
    int rowbase = blockIdx.x * 128;

    // ---- W tile fill: transpose to Wt[n][k], hi/lo ----
    #pragma unroll
    for (int idx = tid; idx < K * Nn; idx += 256) {
        int k = idx / Nn, n2 = idx - k * Nn;
        float v = __ldg(&W[idx]);
        __nv_bfloat16 h = __float2bfloat16(v);
        __nv_bfloat16 l = __float2bfloat16(v - __bfloat162float(h));
        wHi[n2 * PA + k] = h;
        wLo[n2 * PA + k] = l;
    }
    __syncthreads();

    int gp = lane >> 2, tig = lane & 3;
    int r0 = rowbase + wid * 16 + gp;
    int r1 = r0 + 8;
    int r0c = min(r0, M - 1), r1c = min(r1, M - 1);
    const float* x0 = X + (size_t)r0c * K + tig * 2;
    const float* x1 = X + (size_t)r1c * K + tig * 2;

    // ldmatrix per-lane base address (group g = lane>>3)
    int rowOff = (lane & 7) + ((lane >> 4) << 3);  // +8 rows for groups 2,3
    int kOff   = (lane & 8) ? 8 : 0;               // +8 k for groups 1,3
    uint32_t wHiA = (uint32_t)__cvta_generic_to_shared(wHi) + (rowOff * PA + kOff) * 2;
    uint32_t wLoA = wHiA + (uint32_t)(Nn * PA * 2);

    float acc[NT][4];
    #pragma unroll
    for (int t = 0; t < NT; t++) {
        acc[t][0] = 0.f; acc[t][1] = 0.f; acc[t][2] = 0.f; acc[t][3] = 0.f;
    }

    #pragma unroll
    for (int kt = 0; kt < KS; kt++) {
        int ko = kt * 16;
        float2 p0 = __ldg((const float2*)(x0 + ko));        // row r0, k ko+tig*2
        float2 p1 = __ldg((const float2*)(x0 + ko + 8));    // row r0, k+8
        float2 p2 = __ldg((const float2*)(x1 + ko));        // row r1, k
        float2 p3 = __ldg((const float2*)(x1 + ko + 8));    // row r1, k+8
        uint32_t ah0 = pack_bf2(p0.x, p0.y);
        uint32_t ah1 = pack_bf2(p2.x, p2.y);
        uint32_t ah2 = pack_bf2(p1.x, p1.y);
        uint32_t ah3 = pack_bf2(p3.x, p3.y);
        uint32_t al0 = lo_pack(p0, ah0);
        uint32_t al1 = lo_pack(p2, ah1);
        uint32_t al2 = lo_pack(p1, ah2);
        uint32_t al3 = lo_pack(p3, ah3);
        #pragma unroll
        for (int nt2 = 0; nt2 < NT / 2; nt2++) {
            uint32_t off = (uint32_t)((nt2 * 16 * PA + ko) * 2);
            uint32_t bh0, bh1, bh2, bh3, bl0, bl1, bl2, bl3;
            ldsm_x4(bh0, bh1, bh2, bh3, wHiA + off);
            ldsm_x4(bl0, bl1, bl2, bl3, wLoA + off);
            mma_bf16(acc[2 * nt2],     ah0, ah1, ah2, ah3, bh0, bh1);
            mma_bf16(acc[2 * nt2],     ah0, ah1, ah2, ah3, bl0, bl1);
            mma_bf16(acc[2 * nt2],     al0, al1, al2, al3, bh0, bh1);
            mma_bf16(acc[2 * nt2 + 1], ah0, ah1, ah2, ah3, bh2, bh3);
            mma_bf16(acc[2 * nt2 + 1], ah0, ah1, ah2, ah3, bl2, bl3);
            mma_bf16(acc[2 * nt2 + 1], al0, al1, al2, al3, bh2, bh3);
        }
    }

    // ---- epilogue ----
    #pragma unroll
    for (int nt = 0; nt < NT; nt++) {
        int col = nt * 8 + tig * 2;
        float bx = 0.f, by = 0.f;
        if (bias) {
            float2 bv = __ldg((const float2*)&bias[col]);
            bx = bv.x; by = bv.y;
        }
        if (r0 < M)
            *(float2*)(out + (size_t)r0 * Nn + col) =
                make_float2(acc[nt][0] + bx, acc[nt][1] + by);
        if (r1 < M)
            *(float2*)(out + (size_t)r1 * Nn + col) =
                make_float2(acc[nt][2] + bx, acc[nt][3] + by);
    }
}

// ---------------- aggregation: unified dinv form, 4 edges/warp-iter ----------------
__global__ void agg64_kernel(const float* __restrict__ hs,
                             const float* __restrict__ bias,
                             float* __restrict__ out,
                             int n, int relu) {
    int w = (blockIdx.x * blockDim.x + threadIdx.x) >> 5;
    if (w >= n) return;
    int lane = threadIdx.x & 31;
    int half = lane >> 4;
    int q = lane & 15;
    const float4* hs4 = (const float4*)hs;
    float ax = 0.f, ay = 0.f, az = 0.f, aw = 0.f;
    int s = g_rowptr[w], e = g_rowptr[w + 1];
    int i = s + half;
    for (; i + 2 < e; i += 4) {
        int u0 = __ldg(&g_col[i]);
        int u1 = __ldg(&g_col[i + 2]);
        float d0 = __ldg(&g_dinv[u0]);
        float d1 = __ldg(&g_dinv[u1]);
        float4 v0 = __ldg(&hs4[u0 * 16 + q]);
        float4 v1 = __ldg(&hs4[u1 * 16 + q]);
        ax += d0 * v0.x + d1 * v1.x;
        ay += d0 * v0.y + d1 * v1.y;
        az += d0 * v0.z + d1 * v1.z;
        aw += d0 * v0.w + d1 * v1.w;
    }
    if (i < e) {
        int u = __ldg(&g_col[i]);
        float d = __ldg(&g_dinv[u]);
        float4 v = __ldg(&hs4[u * 16 + q]);
        ax += d * v.x; ay += d * v.y; az += d * v.z; aw += d * v.w;
    }
    ax += __shfl_xor_sync(0xffffffffu, ax, 16);
    ay += __shfl_xor_sync(0xffffffffu, ay, 16);
    az += __shfl_xor_sync(0xffffffffu, az, 16);
    aw += __shfl_xor_sync(0xffffffffu, aw, 16);
    float4 sv = __ldg(&hs4[w * 16 + q]);
    float dv = __ldg(&g_dinv[w]);
    ax += sv.x * dv; ay += sv.y * dv; az += sv.z * dv; aw += sv.w * dv;
    ax *= dv; ay *= dv; az *= dv; aw *= dv;
    if (bias) {
        float4 bv = __ldg(&((const float4*)bias)[q]);
        ax += bv.x; ay += bv.y; az += bv.z; aw += bv.w;
    }
    if (relu) {
        ax = fmaxf(ax, 0.f); ay = fmaxf(ay, 0.f);
        az = fmaxf(az, 0.f); aw = fmaxf(aw, 0.f);
    }
    if (lane < 16) ((float4*)out)[w * 16 + q] = make_float4(ax, ay, az, aw);
}

// ---------------- host launcher ----------------
extern "C" void kernel_launch(void* const* d_in, const int* in_sizes, int n_in,
                              void* d_out, int out_size) {
    const float* x  = (const float*)d_in[0];
    const int*   ei = (const int*)d_in[1];
    const float* W1 = (const float*)d_in[2];
    const float* b1 = (const float*)d_in[3];
    const float* W2 = (const float*)d_in[4];
    const float* b2 = (const float*)d_in[5];
    const float* W3 = (const float*)d_in[6];
    const float* b3 = (const float*)d_in[7];
    float* out = (float*)d_out;

    int hid   = in_sizes[3];            // 64
    int odim  = in_sizes[7];            // 112
    int indim = in_sizes[2] / hid;      // 128
    int n     = in_sizes[0] / indim;    // 100000
    int e     = in_sizes[1] / 2;        // 1600000
    const int* src = ei;
    const int* dst = ei + e;

    float *hs_p, *ag_p;
    cudaGetSymbolAddress((void**)&hs_p, g_hs);
    cudaGetSymbolAddress((void**)&ag_p, g_ag);

    int nb = (n + 1023) / 1024;
    int aggBlocks = (n * 32 + 255) / 256;
    int gGrid = (n + 127) / 128;

    // smem: Nn*(K+8)*2 bf16 * 2 bytes  (all <= 35 KB, within default 48 KB)
    auto smem_sz = [](int K, int Nn) { return Nn * (K + 8) * 2 * 2; };

    zero_kernel<<<(n + 255) / 256, 256>>>(n);                          // 0
    hist_kernel<<<(e + 255) / 256, 256>>>(dst, e);                     // 1
    scan_blocks<<<nb, 1024>>>(n);                                      // 2
    // gemm1 is CSR-independent: at launch index 3 so ncu profiles it
    gemm_mma_kernel<8, 8><<<gGrid, 256, smem_sz(128, 64)>>>(x, W1, hs_p, n, nullptr);
    scan_partials<<<1, 128>>>(nb, n);                                  // 4
    finalize_kernel<<<(n + 255) / 256, 256>>>(n);                      // 5
    scatter_kernel<<<(e + 255) / 256, 256>>>(src, dst, e);             // 6

    agg64_kernel<<<aggBlocks, 256>>>(hs_p, b1, ag_p, n, 1);            // 7
    gemm_mma_kernel<4, 8><<<gGrid, 256, smem_sz(64, 64)>>>(ag_p, W2, hs_p, n, nullptr);
    agg64_kernel<<<aggBlocks, 256>>>(hs_p, b2, ag_p, n, 1);
    agg64_kernel<<<aggBlocks, 256>>>(ag_p, nullptr, hs_p, n, 0);
    gemm_mma_kernel<4, 14><<<gGrid, 256, smem_sz(64, 112)>>>(hs_p, W3, out, n, b3);
}